// round 8
// baseline (speedup 1.0000x reference)
#include <cuda_runtime.h>
#include <cuda_fp16.h>
#include <mma.h>
#include <cstdint>

using namespace nvcuda;

// Problem constants
#define BSZ   32
#define TN    512
#define DN    256
#define FN    256
#define ROWS  (BSZ * TN)        // 16384
#define KSUM  768               // 3 * 256
#define MEL   2048
#define GROWS (BSZ * MEL)       // 65536 gather rows
#define OUT_LR_ELEMS (BSZ * MEL * DN)   // 16777216

// GEMM tiling (fp16 m16n16k16), warp tile 64x64, BK=64 halves, 3-stage cp.async
#define BM       128
#define BKH      64
#define LDA      72              // padded leading dim in halves (144B rows)
#define NCHUNK   12              // 768 / 64
#define NSTAGE   3
#define NTHREADS 256
#define STAGE_LD 264             // fp32 epilogue stage leading dim

#define CONV_CTAS (ROWS / BM)    // 128
#define GTAIL     20             // gather tail CTAs (idle SMs on a 148-SM chip)

// ---------------- device scratch ----------------
__device__ __half g_xh[ROWS * DN];      // x in fp16 (RN)
__device__ __half g_h1h[ROWS * FN];     // conv1 out (LN+relu), fp16 (RN)
__device__ __half g_w1h[KSUM * FN];     // w transposed [f][kk], kk=k*256+d
__device__ __half g_w2h[KSUM * FN];
__device__ int    g_map[GROWS];

// ---------------- smem layout (bytes) ----------------
#define STG_STRIDE 55296
#define OFF_B_IN_STG 18432
#define OFF_STAGE  0
#define OFF_BIAS   165888
#define OFF_GAMMA  (OFF_BIAS  + 1024)
#define OFF_BETA   (OFF_GAMMA + 1024)
#define OFF_LW     (OFF_BETA  + 1024)
#define SMEM_BYTES (OFF_LW + 1024)      // 169984

__device__ __forceinline__ float warp_sum(float v) {
    v += __shfl_xor_sync(0xffffffffu, v, 16);
    v += __shfl_xor_sync(0xffffffffu, v, 8);
    v += __shfl_xor_sync(0xffffffffu, v, 4);
    v += __shfl_xor_sync(0xffffffffu, v, 2);
    v += __shfl_xor_sync(0xffffffffu, v, 1);
    return v;
}

__device__ __forceinline__ void cp16(uint32_t dst, const void* src, int szbytes) {
    asm volatile("cp.async.ca.shared.global [%0], [%1], 16, %2;"
                 :: "r"(dst), "l"(src), "r"(szbytes));
}

// ============================================================
// Fused prep kernel (512 threads/block):
//   blocks [0, 384)      : convert weights (transpose + fp16)
//   blocks [384, 2432)   : convert x to fp16
//   blocks [2432, 2464)  : per-batch duration scan -> frame map
// ============================================================
#define PREP_WB   384
#define PREP_XB   2048
#define PREP_GRID (PREP_WB + PREP_XB + BSZ)

__global__ void __launch_bounds__(512)
prep_kernel(const float* __restrict__ w1, const float* __restrict__ w2,
            const float* __restrict__ x,  const int* __restrict__ target) {
    const int blk = blockIdx.x;
    if (blk < PREP_WB) {
        int i = blk * 512 + threadIdx.x;          // i < KSUM*FN = 196608
        int f  = i / KSUM;
        int kk = i - f * KSUM;
        int k  = kk >> 8;
        int d  = kk & 255;
        int src = f * KSUM + d * 3 + k;           // w[f][d][k]
        g_w1h[i] = __float2half_rn(w1[src]);
        g_w2h[i] = __float2half_rn(w2[src]);
    } else if (blk < PREP_WB + PREP_XB) {
        int i = (blk - PREP_WB) * 512 + threadIdx.x;   // float4 units
        float4 v = ((const float4*)x)[i];
        __half2 lo = __floats2half2_rn(v.x, v.y);
        __half2 hi = __floats2half2_rn(v.z, v.w);
        uint2 pk;
        pk.x = *(uint32_t*)&lo;
        pk.y = *(uint32_t*)&hi;
        ((uint2*)g_xh)[i] = pk;
    } else {
        __shared__ int s[TN];
        const int b = blk - PREP_WB - PREP_XB;
        const int t = threadIdx.x;                 // 512 == TN
        const int dur = target[b * TN + t];
        s[t] = dur;
        __syncthreads();
        for (int off = 1; off < TN; off <<= 1) {
            int v = s[t];
            int u = (t >= off) ? s[t - off] : 0;
            __syncthreads();
            s[t] = v + u;
            __syncthreads();
        }
        const int end_   = s[t];
        const int start_ = end_ - dur;
        for (int m = t; m < MEL; m += TN) g_map[b * MEL + m] = -1;
        __syncthreads();
        if (start_ < MEL) {
            int e = end_ < MEL ? end_ : MEL;
            for (int m = start_; m < e; m++) g_map[b * MEL + m] = t;
        }
    }
}

// ============================================================
// fp16 wmma conv GEMM (CTAs 0..127, identical to R6) + gather tail CTAs
// (CTAs 128..147: pure LR gather on otherwise-idle SMs, half of GROWS
//  per conv launch; exact fp32 row copy -> output 0 stays bit-exact).
// ============================================================
template <bool FINAL>
__global__ void __launch_bounds__(NTHREADS)
conv_wmma_kernel(const __half* __restrict__ in,
                 const __half* __restrict__ wh,
                 const float* __restrict__ bias,
                 const float* __restrict__ gamma,
                 const float* __restrict__ beta,
                 const float* __restrict__ lw,
                 const float* __restrict__ lb,
                 const float* __restrict__ xf,     // fp32 x for gather
                 float* __restrict__ gout,         // gather output base
                 __half* __restrict__ outh,
                 float* __restrict__ outf) {
    const int tid = threadIdx.x;

    // ---------------- gather tail blocks ----------------
    if (blockIdx.x >= CONV_CTAS) {
        const int gb   = blockIdx.x - CONV_CTAS;        // 0..GTAIL-1
        const int half = FINAL ? GROWS / 2 : 0;
        const int seg  = tid & 63;                      // float4 within row
        const int rof  = tid >> 6;                      // 0..3
        for (int r4 = gb * 4; r4 < GROWS / 2; r4 += GTAIL * 4) {
            const int row = half + r4 + rof;
            const int t   = g_map[row];
            const int b   = row >> 11;                  // / MEL
            float4 v = make_float4(0.f, 0.f, 0.f, 0.f);
            if (t >= 0)
                v = ((const float4*)(xf + (size_t)(b * TN + t) * DN))[seg];
            ((float4*)gout)[(size_t)row * 64 + seg] = v;
        }
        return;
    }

    // ---------------- conv GEMM blocks (identical to R6) ----------------
    extern __shared__ char smem[];
    const uint32_t sbase = (uint32_t)__cvta_generic_to_shared(smem);
    const int wid  = tid >> 5;
    const int lane = tid & 31;
    const int wm   = wid & 1;          // warp row group -> 64 rows
    const int wn   = wid >> 1;         // warp col group -> 64 cols
    const int rowBase = blockIdx.x * BM;

    // stage params
    ((float*)(smem + OFF_BIAS))[tid]  = bias[tid];
    ((float*)(smem + OFF_GAMMA))[tid] = gamma[tid];
    ((float*)(smem + OFF_BETA))[tid]  = beta[tid];
    if (FINAL) ((float*)(smem + OFF_LW))[tid] = lw[tid];

    wmma::fragment<wmma::accumulator, 16, 16, 16, float> acc[4][4];
#pragma unroll
    for (int mt = 0; mt < 4; mt++)
#pragma unroll
        for (int nt = 0; nt < 4; nt++) wmma::fill_fragment(acc[mt][nt], 0.f);

    auto load_tiles = [&](int c) {
        const int slot = c % NSTAGE;
        const uint32_t As = sbase + slot * STG_STRIDE;
        const uint32_t Bs = As + OFF_B_IN_STG;
        const int k   = c >> 2;
        const int d0  = (c & 3) << 6;
        const int km1 = k - 1;
#pragma unroll
        for (int i = 0; i < 4; i++) {      // A: 1024 16B units
            const int u   = i * NTHREADS + tid;
            const int row = u >> 3, seg = u & 7;
            const int gr  = rowBase + row;
            const int tpos = (gr & (TN - 1)) + km1;
            const bool p = (tpos >= 0 && tpos < TN);
            const __half* src = p ? (in + (size_t)(gr + km1) * DN + d0 + seg * 8) : in;
            cp16(As + row * (LDA * 2) + seg * 16, src, p ? 16 : 0);
        }
#pragma unroll
        for (int i = 0; i < 8; i++) {      // B: 2048 16B units
            const int u = i * NTHREADS + tid;
            const int f = u >> 3, seg = u & 7;
            cp16(Bs + f * (LDA * 2) + seg * 16,
                 wh + (size_t)f * KSUM + c * BKH + seg * 8, 16);
        }
        asm volatile("cp.async.commit_group;" ::: "memory");
    };

    load_tiles(0);
    load_tiles(1);

    for (int c = 0; c < NCHUNK; c++) {
        if (c < NCHUNK - 1) {
            asm volatile("cp.async.wait_group 1;" ::: "memory");
        } else {
            asm volatile("cp.async.wait_group 0;" ::: "memory");
        }
        __syncthreads();
        if (c + 2 < NCHUNK) load_tiles(c + 2);

        const int slot = c % NSTAGE;
        const __half* As = (const __half*)(smem + slot * STG_STRIDE);
        const __half* Bs = (const __half*)(smem + slot * STG_STRIDE + OFF_B_IN_STG);
#pragma unroll
        for (int ks = 0; ks < 4; ks++) {
            wmma::fragment<wmma::matrix_a, 16, 16, 16, __half, wmma::row_major> af[4];
            wmma::fragment<wmma::matrix_b, 16, 16, 16, __half, wmma::col_major> bf[4];
#pragma unroll
            for (int mt = 0; mt < 4; mt++)
                wmma::load_matrix_sync(af[mt], As + (wm * 64 + mt * 16) * LDA + ks * 16, LDA);
#pragma unroll
            for (int nt = 0; nt < 4; nt++)
                wmma::load_matrix_sync(bf[nt], Bs + (wn * 64 + nt * 16) * LDA + ks * 16, LDA);
#pragma unroll
            for (int mt = 0; mt < 4; mt++)
#pragma unroll
                for (int nt = 0; nt < 4; nt++)
                    wmma::mma_sync(acc[mt][nt], af[mt], bf[nt], acc[mt][nt]);
        }
    }
    __syncthreads();   // tiles dead; reuse smem as fp32 stage

    // ---- stage accumulators to smem ----
    float* stage = (float*)(smem + OFF_STAGE);
#pragma unroll
    for (int mt = 0; mt < 4; mt++)
#pragma unroll
        for (int nt = 0; nt < 4; nt++)
            wmma::store_matrix_sync(stage + (wm * 64 + mt * 16) * STAGE_LD + wn * 64 + nt * 16,
                                    acc[mt][nt], STAGE_LD, wmma::mem_row_major);
    __syncthreads();

    // ---- epilogue: each of 8 warps owns 16 rows; lane owns 8 cols ----
    const float* sb_bias = (const float*)(smem + OFF_BIAS);
    const float* sb_g    = (const float*)(smem + OFF_GAMMA);
    const float* sb_b    = (const float*)(smem + OFF_BETA);
    const float* sb_lw   = (const float*)(smem + OFF_LW);
    const int c0 = lane * 8;

    float bia[8], gam[8], bet[8], lwv[8];
#pragma unroll
    for (int j = 0; j < 8; j++) {
        bia[j] = sb_bias[c0 + j];
        gam[j] = sb_g[c0 + j];
        bet[j] = sb_b[c0 + j];
        if (FINAL) lwv[j] = sb_lw[c0 + j];
    }
    const float lb0 = FINAL ? __ldg(lb) : 0.f;

#pragma unroll
    for (int i = 0; i < 16; i++) {
        const int row = wid * 16 + i;
        const int gr  = rowBase + row;
        float v[8];
        float s = 0.f;
#pragma unroll
        for (int j = 0; j < 8; j++) {
            v[j] = stage[row * STAGE_LD + c0 + j] + bia[j];
            s += v[j];
        }
        s = warp_sum(s);
        const float mean = s * (1.f / 256.f);
        float q = 0.f;
#pragma unroll
        for (int j = 0; j < 8; j++) {
            float d = v[j] - mean;
            q += d * d;
        }
        q = warp_sum(q);
        const float inv = rsqrtf(q * (1.f / 256.f) + 1e-5f);

        if (!FINAL) {
            __half2 hv[4];
#pragma unroll
            for (int j = 0; j < 4; j++) {
                float za = (v[2*j]   - mean) * inv * gam[2*j]   + bet[2*j];
                float zb = (v[2*j+1] - mean) * inv * gam[2*j+1] + bet[2*j+1];
                hv[j] = __floats2half2_rn(fmaxf(za, 0.f), fmaxf(zb, 0.f));
            }
            *(uint4*)(outh + (size_t)gr * FN + c0) = *(uint4*)hv;
        } else {
            float p = 0.f;
#pragma unroll
            for (int j = 0; j < 8; j++) {
                float z = (v[j] - mean) * inv * gam[j] + bet[j];
                p = fmaf(fmaxf(z, 0.f), lwv[j], p);
            }
            p = warp_sum(p);
            if (lane == 0) outf[gr] = p + lb0;
        }
    }
}

// ============================================================
// launch
// ============================================================
extern "C" void kernel_launch(void* const* d_in, const int* in_sizes, int n_in,
                              void* d_out, int out_size) {
    const float* x   = (const float*)d_in[0];
    const float* w1  = (const float*)d_in[1];
    const float* b1  = (const float*)d_in[2];
    const float* g1  = (const float*)d_in[3];
    const float* be1 = (const float*)d_in[4];
    const float* w2  = (const float*)d_in[5];
    const float* b2  = (const float*)d_in[6];
    const float* g2  = (const float*)d_in[7];
    const float* be2 = (const float*)d_in[8];
    const float* lw  = (const float*)d_in[9];
    const float* lb  = (const float*)d_in[10];
    const int* target = (const int*)d_in[11];
    float* out = (float*)d_out;

    __half *xh, *h1h, *w1h, *w2h;
    cudaGetSymbolAddress((void**)&xh,  g_xh);
    cudaGetSymbolAddress((void**)&h1h, g_h1h);
    cudaGetSymbolAddress((void**)&w1h, g_w1h);
    cudaGetSymbolAddress((void**)&w2h, g_w2h);

    cudaFuncSetAttribute(conv_wmma_kernel<false>,
                         cudaFuncAttributeMaxDynamicSharedMemorySize, SMEM_BYTES);
    cudaFuncSetAttribute(conv_wmma_kernel<true>,
                         cudaFuncAttributeMaxDynamicSharedMemorySize, SMEM_BYTES);

    prep_kernel<<<PREP_GRID, 512>>>(w1, w2, x, target);

    conv_wmma_kernel<false><<<CONV_CTAS + GTAIL, NTHREADS, SMEM_BYTES>>>(
        xh, w1h, b1, g1, be1, nullptr, nullptr, x, out, h1h, nullptr);
    conv_wmma_kernel<true><<<CONV_CTAS + GTAIL, NTHREADS, SMEM_BYTES>>>(
        h1h, w2h, b2, g2, be2, lw, lb, x, out, nullptr, out + OUT_LR_ELEMS);
}

// round 9
// speedup vs baseline: 5.5988x; 5.5988x over previous
#include <cuda_runtime.h>
#include <cuda_fp16.h>
#include <mma.h>
#include <cstdint>

using namespace nvcuda;

// Problem constants
#define BSZ   32
#define TN    512
#define DN    256
#define FN    256
#define ROWS  (BSZ * TN)        // 16384
#define KSUM  768               // 3 * 256
#define MEL   2048
#define GROWS (BSZ * MEL)       // 65536 gather rows
#define OUT_LR_ELEMS (BSZ * MEL * DN)   // 16777216

// GEMM tiling (fp16 m16n16k16), warp tile 64x64, BK=64 halves, 3-stage cp.async
#define BM       128
#define BKH      64
#define LDA      72              // padded leading dim in halves (144B rows)
#define NCHUNK   12              // 768 / 64
#define NSTAGE   3
#define NTHREADS 256
#define STAGE_LD 264             // fp32 epilogue stage leading dim

// ---------------- device scratch ----------------
__device__ __half g_xh[ROWS * DN];      // x in fp16 (RN)
__device__ __half g_h1h[ROWS * FN];     // conv1 out (LN+relu), fp16 (RN)
__device__ __half g_w1h[KSUM * FN];     // w transposed [f][kk], kk=k*256+d
__device__ __half g_w2h[KSUM * FN];
__device__ int    g_map[GROWS];

// ---------------- smem layout (bytes) ----------------
#define STG_STRIDE 55296
#define OFF_B_IN_STG 18432
#define OFF_STAGE  0
#define OFF_BIAS   165888
#define OFF_GAMMA  (OFF_BIAS  + 1024)
#define OFF_BETA   (OFF_GAMMA + 1024)
#define OFF_LW     (OFF_BETA  + 1024)
#define SMEM_BYTES (OFF_LW + 1024)      // 169984

__device__ __forceinline__ float warp_sum(float v) {
    v += __shfl_xor_sync(0xffffffffu, v, 16);
    v += __shfl_xor_sync(0xffffffffu, v, 8);
    v += __shfl_xor_sync(0xffffffffu, v, 4);
    v += __shfl_xor_sync(0xffffffffu, v, 2);
    v += __shfl_xor_sync(0xffffffffu, v, 1);
    return v;
}

__device__ __forceinline__ void cp16(uint32_t dst, const void* src, int szbytes) {
    asm volatile("cp.async.ca.shared.global [%0], [%1], 16, %2;"
                 :: "r"(dst), "l"(src), "r"(szbytes));
}

// ============================================================
// Fused prep kernel (512 threads/block):
//   blocks [0, 384)    : convert weights (transpose + fp16), 1 elem/thread
//   blocks [384, 896)  : convert x to fp16, 4 float4/thread (MLP=4)
//   blocks [896, 928)  : per-batch duration scan -> frame map
// ============================================================
#define PREP_WB   384
#define PREP_XB   512
#define PREP_GRID (PREP_WB + PREP_XB + BSZ)

__global__ void __launch_bounds__(512)
prep_kernel(const float* __restrict__ w1, const float* __restrict__ w2,
            const float* __restrict__ x,  const int* __restrict__ target) {
    const int blk = blockIdx.x;
    if (blk < PREP_WB) {
        int i = blk * 512 + threadIdx.x;          // i < KSUM*FN = 196608
        int f  = i / KSUM;
        int kk = i - f * KSUM;
        int k  = kk >> 8;
        int d  = kk & 255;
        int src = f * KSUM + d * 3 + k;           // w[f][d][k]
        g_w1h[i] = __float2half_rn(w1[src]);
        g_w2h[i] = __float2half_rn(w2[src]);
    } else if (blk < PREP_WB + PREP_XB) {
        const int base = (blk - PREP_WB) * 2048 + threadIdx.x;  // float4 units
        float4 v[4];
#pragma unroll
        for (int k = 0; k < 4; k++)
            v[k] = ((const float4*)x)[base + k * 512];
#pragma unroll
        for (int k = 0; k < 4; k++) {
            __half2 lo = __floats2half2_rn(v[k].x, v[k].y);
            __half2 hi = __floats2half2_rn(v[k].z, v[k].w);
            uint2 pk;
            pk.x = *(uint32_t*)&lo;
            pk.y = *(uint32_t*)&hi;
            ((uint2*)g_xh)[base + k * 512] = pk;
        }
    } else {
        __shared__ int s[TN];
        const int b = blk - PREP_WB - PREP_XB;
        const int t = threadIdx.x;                 // 512 == TN
        const int dur = target[b * TN + t];
        s[t] = dur;
        __syncthreads();
        for (int off = 1; off < TN; off <<= 1) {
            int v = s[t];
            int u = (t >= off) ? s[t - off] : 0;
            __syncthreads();
            s[t] = v + u;
            __syncthreads();
        }
        const int end_   = s[t];
        const int start_ = end_ - dur;
        for (int m = t; m < MEL; m += TN) g_map[b * MEL + m] = -1;
        __syncthreads();
        if (start_ < MEL) {
            int e = end_ < MEL ? end_ : MEL;
            for (int m = start_; m < e; m++) g_map[b * MEL + m] = t;
        }
    }
}

// ============================================================
// LR gather, MLP=8: 2048 blocks x 256 threads; warp handles 4 rows,
// 8 independent LDG.128 then 8 STG.128 per thread. Exact fp32 copy.
// ============================================================
__global__ void __launch_bounds__(256)
gather_kernel(const float* __restrict__ x, float* __restrict__ out) {
    const int wid  = threadIdx.x >> 5;
    const int lane = threadIdx.x & 31;
    const int rowBase = blockIdx.x * 32 + wid * 4;   // 4 rows per warp, same batch
    const int b = rowBase >> 11;                     // / MEL (2048 % 4 == 0)

    int t[4];
#pragma unroll
    for (int r = 0; r < 4; r++) t[r] = g_map[rowBase + r];

    float4 v[8];
#pragma unroll
    for (int r = 0; r < 4; r++) {
        if (t[r] >= 0) {
            const float4* src = (const float4*)(x + (size_t)(b * TN + t[r]) * DN);
            v[r * 2]     = src[lane];
            v[r * 2 + 1] = src[lane + 32];
        } else {
            v[r * 2]     = make_float4(0.f, 0.f, 0.f, 0.f);
            v[r * 2 + 1] = make_float4(0.f, 0.f, 0.f, 0.f);
        }
    }
#pragma unroll
    for (int r = 0; r < 4; r++) {
        float4* dst = (float4*)(out + (size_t)(rowBase + r) * DN);
        dst[lane]      = v[r * 2];
        dst[lane + 32] = v[r * 2 + 1];
    }
}

// ============================================================
// fp16 wmma conv GEMM (identical to R6 — the protected core).
// ============================================================
template <bool FINAL>
__global__ void __launch_bounds__(NTHREADS)
conv_wmma_kernel(const __half* __restrict__ in,
                 const __half* __restrict__ wh,
                 const float* __restrict__ bias,
                 const float* __restrict__ gamma,
                 const float* __restrict__ beta,
                 const float* __restrict__ lw,
                 const float* __restrict__ lb,
                 __half* __restrict__ outh,
                 float* __restrict__ outf) {
    extern __shared__ char smem[];
    const uint32_t sbase = (uint32_t)__cvta_generic_to_shared(smem);
    const int tid  = threadIdx.x;
    const int wid  = tid >> 5;
    const int lane = tid & 31;
    const int wm   = wid & 1;          // warp row group -> 64 rows
    const int wn   = wid >> 1;         // warp col group -> 64 cols
    const int rowBase = blockIdx.x * BM;

    // stage params
    ((float*)(smem + OFF_BIAS))[tid]  = bias[tid];
    ((float*)(smem + OFF_GAMMA))[tid] = gamma[tid];
    ((float*)(smem + OFF_BETA))[tid]  = beta[tid];
    if (FINAL) ((float*)(smem + OFF_LW))[tid] = lw[tid];

    wmma::fragment<wmma::accumulator, 16, 16, 16, float> acc[4][4];
#pragma unroll
    for (int mt = 0; mt < 4; mt++)
#pragma unroll
        for (int nt = 0; nt < 4; nt++) wmma::fill_fragment(acc[mt][nt], 0.f);

    auto load_tiles = [&](int c) {
        const int slot = c % NSTAGE;
        const uint32_t As = sbase + slot * STG_STRIDE;
        const uint32_t Bs = As + OFF_B_IN_STG;
        const int k   = c >> 2;
        const int d0  = (c & 3) << 6;
        const int km1 = k - 1;
#pragma unroll
        for (int i = 0; i < 4; i++) {      // A: 1024 16B units
            const int u   = i * NTHREADS + tid;
            const int row = u >> 3, seg = u & 7;
            const int gr  = rowBase + row;
            const int tpos = (gr & (TN - 1)) + km1;
            const bool p = (tpos >= 0 && tpos < TN);
            const __half* src = p ? (in + (size_t)(gr + km1) * DN + d0 + seg * 8) : in;
            cp16(As + row * (LDA * 2) + seg * 16, src, p ? 16 : 0);
        }
#pragma unroll
        for (int i = 0; i < 8; i++) {      // B: 2048 16B units
            const int u = i * NTHREADS + tid;
            const int f = u >> 3, seg = u & 7;
            cp16(Bs + f * (LDA * 2) + seg * 16,
                 wh + (size_t)f * KSUM + c * BKH + seg * 8, 16);
        }
        asm volatile("cp.async.commit_group;" ::: "memory");
    };

    load_tiles(0);
    load_tiles(1);

    for (int c = 0; c < NCHUNK; c++) {
        if (c < NCHUNK - 1) {
            asm volatile("cp.async.wait_group 1;" ::: "memory");
        } else {
            asm volatile("cp.async.wait_group 0;" ::: "memory");
        }
        __syncthreads();
        if (c + 2 < NCHUNK) load_tiles(c + 2);

        const int slot = c % NSTAGE;
        const __half* As = (const __half*)(smem + slot * STG_STRIDE);
        const __half* Bs = (const __half*)(smem + slot * STG_STRIDE + OFF_B_IN_STG);
#pragma unroll
        for (int ks = 0; ks < 4; ks++) {
            wmma::fragment<wmma::matrix_a, 16, 16, 16, __half, wmma::row_major> af[4];
            wmma::fragment<wmma::matrix_b, 16, 16, 16, __half, wmma::col_major> bf[4];
#pragma unroll
            for (int mt = 0; mt < 4; mt++)
                wmma::load_matrix_sync(af[mt], As + (wm * 64 + mt * 16) * LDA + ks * 16, LDA);
#pragma unroll
            for (int nt = 0; nt < 4; nt++)
                wmma::load_matrix_sync(bf[nt], Bs + (wn * 64 + nt * 16) * LDA + ks * 16, LDA);
#pragma unroll
            for (int mt = 0; mt < 4; mt++)
#pragma unroll
                for (int nt = 0; nt < 4; nt++)
                    wmma::mma_sync(acc[mt][nt], af[mt], bf[nt], acc[mt][nt]);
        }
    }
    __syncthreads();   // tiles dead; reuse smem as fp32 stage

    // ---- stage accumulators to smem ----
    float* stage = (float*)(smem + OFF_STAGE);
#pragma unroll
    for (int mt = 0; mt < 4; mt++)
#pragma unroll
        for (int nt = 0; nt < 4; nt++)
            wmma::store_matrix_sync(stage + (wm * 64 + mt * 16) * STAGE_LD + wn * 64 + nt * 16,
                                    acc[mt][nt], STAGE_LD, wmma::mem_row_major);
    __syncthreads();

    // ---- epilogue: each of 8 warps owns 16 rows; lane owns 8 cols ----
    const float* sb_bias = (const float*)(smem + OFF_BIAS);
    const float* sb_g    = (const float*)(smem + OFF_GAMMA);
    const float* sb_b    = (const float*)(smem + OFF_BETA);
    const float* sb_lw   = (const float*)(smem + OFF_LW);
    const int c0 = lane * 8;

    float bia[8], gam[8], bet[8], lwv[8];
#pragma unroll
    for (int j = 0; j < 8; j++) {
        bia[j] = sb_bias[c0 + j];
        gam[j] = sb_g[c0 + j];
        bet[j] = sb_b[c0 + j];
        if (FINAL) lwv[j] = sb_lw[c0 + j];
    }
    const float lb0 = FINAL ? __ldg(lb) : 0.f;

#pragma unroll
    for (int i = 0; i < 16; i++) {
        const int row = wid * 16 + i;
        const int gr  = rowBase + row;
        float v[8];
        float s = 0.f;
#pragma unroll
        for (int j = 0; j < 8; j++) {
            v[j] = stage[row * STAGE_LD + c0 + j] + bia[j];
            s += v[j];
        }
        s = warp_sum(s);
        const float mean = s * (1.f / 256.f);
        float q = 0.f;
#pragma unroll
        for (int j = 0; j < 8; j++) {
            float d = v[j] - mean;
            q += d * d;
        }
        q = warp_sum(q);
        const float inv = rsqrtf(q * (1.f / 256.f) + 1e-5f);

        if (!FINAL) {
            __half2 hv[4];
#pragma unroll
            for (int j = 0; j < 4; j++) {
                float za = (v[2*j]   - mean) * inv * gam[2*j]   + bet[2*j];
                float zb = (v[2*j+1] - mean) * inv * gam[2*j+1] + bet[2*j+1];
                hv[j] = __floats2half2_rn(fmaxf(za, 0.f), fmaxf(zb, 0.f));
            }
            *(uint4*)(outh + (size_t)gr * FN + c0) = *(uint4*)hv;
        } else {
            float p = 0.f;
#pragma unroll
            for (int j = 0; j < 8; j++) {
                float z = (v[j] - mean) * inv * gam[j] + bet[j];
                p = fmaf(fmaxf(z, 0.f), lwv[j], p);
            }
            p = warp_sum(p);
            if (lane == 0) outf[gr] = p + lb0;
        }
    }
}

// ============================================================
// launch
// ============================================================
extern "C" void kernel_launch(void* const* d_in, const int* in_sizes, int n_in,
                              void* d_out, int out_size) {
    const float* x   = (const float*)d_in[0];
    const float* w1  = (const float*)d_in[1];
    const float* b1  = (const float*)d_in[2];
    const float* g1  = (const float*)d_in[3];
    const float* be1 = (const float*)d_in[4];
    const float* w2  = (const float*)d_in[5];
    const float* b2  = (const float*)d_in[6];
    const float* g2  = (const float*)d_in[7];
    const float* be2 = (const float*)d_in[8];
    const float* lw  = (const float*)d_in[9];
    const float* lb  = (const float*)d_in[10];
    const int* target = (const int*)d_in[11];
    float* out = (float*)d_out;

    __half *xh, *h1h, *w1h, *w2h;
    cudaGetSymbolAddress((void**)&xh,  g_xh);
    cudaGetSymbolAddress((void**)&h1h, g_h1h);
    cudaGetSymbolAddress((void**)&w1h, g_w1h);
    cudaGetSymbolAddress((void**)&w2h, g_w2h);

    cudaFuncSetAttribute(conv_wmma_kernel<false>,
                         cudaFuncAttributeMaxDynamicSharedMemorySize, SMEM_BYTES);
    cudaFuncSetAttribute(conv_wmma_kernel<true>,
                         cudaFuncAttributeMaxDynamicSharedMemorySize, SMEM_BYTES);

    prep_kernel<<<PREP_GRID, 512>>>(w1, w2, x, target);
    gather_kernel<<<GROWS / 32, 256>>>(x, out);

    conv_wmma_kernel<false><<<ROWS / BM, NTHREADS, SMEM_BYTES>>>(
        xh, w1h, b1, g1, be1, nullptr, nullptr, h1h, nullptr);
    conv_wmma_kernel<true><<<ROWS / BM, NTHREADS, SMEM_BYTES>>>(
        h1h, w2h, b2, g2, be2, lw, lb, nullptr, out + OUT_LR_ELEMS);
}